// round 9
// baseline (speedup 1.0000x reference)
#include <cuda_runtime.h>
#include <math.h>

#define NM 1024
#define HH 256
#define WW 256
#define HW (HH * WW)
#define CHUNK (HW / 4)            // 16384 floats per chunk (64 rows)
#define NBLK (NM * 4)

#define PRED_IOU_THRESH   0.88f
#define STABILITY_THRESH  0.95f
#define BOX_NMS_THRESH    0.7f

// Scratch (device globals: no allocation allowed)
__device__ int      g_part[NM * 4 * 8]; // per (mask,chunk): hi,lo,minx,maxx,miny,maxy,pad,pad
__device__ float    g_gated[NM];        // iou * keep
__device__ unsigned g_done;             // zero-initialized; reset by last block each launch
// NMS scratch (tiny, L2-resident)
__device__ float  g_cscore[NM];
__device__ short  g_cidx[NM];
__device__ float4 g_cbox[NM];
__device__ float  g_rscore[NM];
__device__ short  g_ridx[NM];
__device__ float4 g_rb[NM];
__device__ int    g_rkeep[NM];

__device__ __forceinline__ float box_iou(const float4 a, const float4 b) {
    const float x0 = fmaxf(a.x, b.x);
    const float y0 = fmaxf(a.y, b.y);
    const float x1 = fminf(a.z, b.z);
    const float y1 = fminf(a.w, b.w);
    const float inter = fmaxf(x1 - x0, 0.f) * fmaxf(y1 - y0, 0.f);
    const float aa = fmaxf(a.z - a.x, 0.f) * fmaxf(a.w - a.y, 0.f);
    const float ab = fmaxf(b.z - b.x, 0.f) * fmaxf(b.w - b.y, 0.f);
    return inter / fmaxf(aa + ab - inter, 1e-6f);
}

// ---------------------------------------------------------------------------
// Kernel 1: per-chunk stats + zero-fill, with NMS fused into the last block.
// 4096 blocks (mask,chunk), 256 threads, 16 float4/thread, streaming.
// ---------------------------------------------------------------------------
__global__ __launch_bounds__(256) void stats_zero_nms_kernel(const float* __restrict__ logits,
                                                             float* __restrict__ out,
                                                             const float* __restrict__ iou_preds,
                                                             float* __restrict__ out_tail,
                                                             int write_keep, int write_boxes) {
    const int b = blockIdx.x;
    const int n = b >> 2;
    const int c = b & 3;
    const size_t off = (size_t)n * HW + (size_t)c * CHUNK;
    const float4* __restrict__ p = (const float4*)(logits + off);
    float4* __restrict__ o = (float4*)(out + off);
    const int t = threadIdx.x;

    int hi = 0, lo = 0;
    unsigned rowmask = 0u;
    int colbits = 0;
    const float4 z = make_float4(0.f, 0.f, 0.f, 0.f);

#pragma unroll 8
    for (int k = 0; k < 16; k++) {
        const int i4 = t + (k << 8);
        const float4 v = __ldcs(&p[i4]);
        __stcs(&o[i4], z);
        hi += (v.x > 1.f) + (v.y > 1.f) + (v.z > 1.f) + (v.w > 1.f);
        lo += (v.x > -1.f) + (v.y > -1.f) + (v.z > -1.f) + (v.w > -1.f);
        const int bits = (int)(v.x > 0.f) | ((int)(v.y > 0.f) << 1)
                       | ((int)(v.z > 0.f) << 2) | ((int)(v.w > 0.f) << 3);
        colbits |= bits;
        rowmask |= (bits ? 1u : 0u) << k;
    }

    int minx = WW, maxx = -1, miny = HH, maxy = -1;
    if (colbits) {
        const int x0 = (t & 63) << 2;
        minx = x0 + (__ffs(colbits) - 1);
        maxx = x0 + (31 - __clz(colbits));
    }
    if (rowmask) {
        const int r0 = (t >> 6) + (c << 6);
        miny = r0 + ((__ffs(rowmask) - 1) << 2);
        maxy = r0 + ((31 - __clz((int)rowmask)) << 2);
    }

    // warp reduce
#pragma unroll
    for (int oo = 16; oo > 0; oo >>= 1) {
        hi   += __shfl_xor_sync(0xffffffffu, hi, oo);
        lo   += __shfl_xor_sync(0xffffffffu, lo, oo);
        minx  = min(minx, __shfl_xor_sync(0xffffffffu, minx, oo));
        maxx  = max(maxx, __shfl_xor_sync(0xffffffffu, maxx, oo));
        miny  = min(miny, __shfl_xor_sync(0xffffffffu, miny, oo));
        maxy  = max(maxy, __shfl_xor_sync(0xffffffffu, maxy, oo));
    }

    __shared__ int s[8][6];
    __shared__ int s_islast;
    __shared__ int s_cnt;
    const int w = t >> 5, l = t & 31;
    if (l == 0) {
        s[w][0] = hi;   s[w][1] = lo;
        s[w][2] = minx; s[w][3] = maxx;
        s[w][4] = miny; s[w][5] = maxy;
    }
    __syncthreads();
    if (t == 0) {
#pragma unroll
        for (int i = 1; i < 8; i++) {
            hi += s[i][0]; lo += s[i][1];
            minx = min(minx, s[i][2]); maxx = max(maxx, s[i][3]);
            miny = min(miny, s[i][4]); maxy = max(maxy, s[i][5]);
        }
        int4* pp = (int4*)g_part;
        pp[b * 2]     = make_int4(hi, lo, minx, maxx);
        pp[b * 2 + 1] = make_int4(miny, maxy, 0, 0);

        __threadfence();                              // publish partials
        const unsigned v = atomicAdd(&g_done, 1u);
        s_islast = (v == (unsigned)(NBLK - 1));
        s_cnt = 0;
    }
    __syncthreads();
    if (!s_islast) return;

    // ======================= LAST BLOCK: fused NMS ========================
    __threadfence();                                  // acquire all partials

    // 1) combine + filter + compact (each thread: 4 masks)
    const int4* pp = (const int4*)g_part;
    for (int m = t; m < NM; m += 256) {
        int Hi = 0, Lo = 0, mnx = WW, mxx = -1, mny = HH, mxy = -1;
#pragma unroll
        for (int cc = 0; cc < 4; cc++) {
            const int4 a  = pp[(m * 4 + cc) * 2];
            const int4 bq = pp[(m * 4 + cc) * 2 + 1];
            Hi += a.x; Lo += a.y;
            mnx = min(mnx, a.z); mxx = max(mxx, a.w);
            mny = min(mny, bq.x); mxy = max(mxy, bq.y);
        }
        float4 box;
        if (mxx < 0) box = make_float4(0.f, 0.f, 0.f, 0.f);
        else box = make_float4((float)mnx, (float)mny, (float)mxx, (float)mxy);

        const float stab = (float)Hi / fmaxf((float)Lo, 1.0f);
        const float score = iou_preds[m];
        const int valid = (score > PRED_IOU_THRESH) && (stab >= STABILITY_THRESH);

        g_gated[m] = 0.f;                              // defaults (overwritten if kept)
        if (write_keep)  out_tail[m] = 0.0f;
        if (write_boxes) ((float4*)(out_tail + NM))[m] = box;

        if (valid) {
            const int slot = atomicAdd(&s_cnt, 1);
            g_cscore[slot] = score;
            g_cidx[slot]   = (short)m;
            g_cbox[slot]   = box;
        }
    }
    __syncthreads();
    const int V = s_cnt;

    // 2) stable descending rank (score desc, original index asc)
    for (int sidx = t; sidx < V; sidx += 256) {
        const float s0 = g_cscore[sidx];
        const short i0 = g_cidx[sidx];
        int rank = 0;
        for (int j = 0; j < V; j++) {
            const float sj = g_cscore[j];
            rank += (sj > s0) || (sj == s0 && g_cidx[j] < i0);
        }
        g_rb[rank]     = g_cbox[sidx];
        g_ridx[rank]   = i0;
        g_rscore[rank] = s0;
        g_rkeep[rank]  = 1;
    }
    __syncthreads();

    // 3) warp-serial greedy suppression (warp 0 only)
    if (t < 32) {
        for (int i = 0; i < V; i++) {
            if (g_rkeep[i]) {
                const float4 bi = g_rb[i];
                for (int j = i + 1 + t; j < V; j += 32) {
                    if (g_rkeep[j] && box_iou(bi, g_rb[j]) > BOX_NMS_THRESH)
                        g_rkeep[j] = 0;
                }
            }
            __syncwarp();
        }
    }
    __syncthreads();

    // 4) scatter results back to original order
    for (int sidx = t; sidx < V; sidx += 256) {
        if (g_rkeep[sidx]) {
            const int m = g_ridx[sidx];
            g_gated[m] = g_rscore[sidx];
            if (write_keep) out_tail[m] = 1.0f;
        }
    }
    __syncthreads();
    if (t == 0) {
        g_done = 0;                                    // reset for next replay
        __threadfence();
    }
}

// ---------------------------------------------------------------------------
// Kernel 2: sparse output fill — only kept masks do work (zeros already
// written by kernel 1). grid (NM, 4) x 256 threads x 16 float4.
// ---------------------------------------------------------------------------
__global__ __launch_bounds__(256) void out_kernel(const float* __restrict__ logits,
                                                  float* __restrict__ out) {
    const int n = blockIdx.x;
    const float g = g_gated[n];
    if (g == 0.f) return;

    const size_t off = (size_t)n * HW + (size_t)blockIdx.y * CHUNK;
    const float4* __restrict__ p = (const float4*)(logits + off);
    float4* __restrict__ o = (float4*)(out + off);
    const int t = threadIdx.x;

#pragma unroll 4
    for (int k = 0; k < 16; k++) {
        const int i = t + (k << 8);
        float4 v = __ldcs(&p[i]);
        v.x = g / (1.f + __expf(-v.x));
        v.y = g / (1.f + __expf(-v.y));
        v.z = g / (1.f + __expf(-v.z));
        v.w = g / (1.f + __expf(-v.w));
        __stcs(&o[i], v);
    }
}

extern "C" void kernel_launch(void* const* d_in, const int* in_sizes, int n_in,
                              void* d_out, int out_size) {
    const float* logits = (const float*)d_in[0];
    const float* iou    = (const float*)d_in[1];
    if (n_in >= 2 && in_sizes[0] == NM) {      // defensive: input order swap
        logits = (const float*)d_in[1];
        iou    = (const float*)d_in[0];
    }
    float* out = (float*)d_out;

    const long long tail = (long long)out_size - (long long)NM * HW;
    const int write_keep  = tail >= NM;
    const int write_boxes = tail >= 5 * NM;

    stats_zero_nms_kernel<<<NBLK, 256>>>(logits, out, iou,
                                         out + (size_t)NM * HW, write_keep, write_boxes);
    out_kernel<<<dim3(NM, 4), 256>>>(logits, out);
}

// round 10
// speedup vs baseline: 1.0890x; 1.0890x over previous
#include <cuda_runtime.h>
#include <math.h>

#define NM 1024
#define HH 256
#define WW 256
#define HW (HH * WW)
#define CHUNK (HW / 4)            // stats chunk: 16384 floats (64 rows)
#define OCHUNK (HW / 16)          // out chunk: 4096 floats (16 rows)
#define NBLK (NM * 4)

#define PRED_IOU_THRESH   0.88f
#define STABILITY_THRESH  0.95f
#define BOX_NMS_THRESH    0.7f

// Scratch (device globals: no allocation allowed)
__device__ int      g_part[NM * 4 * 8]; // per (mask,chunk): hi,lo,minx,maxx,miny,maxy,pad,pad
__device__ float    g_gated[NM];        // iou * keep
__device__ unsigned g_done;             // zero-initialized; reset by last block each launch
// NMS scratch (tiny, L2-resident)
__device__ float  g_cscore[NM];
__device__ short  g_cidx[NM];
__device__ float4 g_cbox[NM];
__device__ float  g_rscore[NM];
__device__ short  g_ridx[NM];
__device__ float4 g_rb[NM];
__device__ int    g_rkeep[NM];

__device__ __forceinline__ float box_iou(const float4 a, const float4 b) {
    const float x0 = fmaxf(a.x, b.x);
    const float y0 = fmaxf(a.y, b.y);
    const float x1 = fminf(a.z, b.z);
    const float y1 = fminf(a.w, b.w);
    const float inter = fmaxf(x1 - x0, 0.f) * fmaxf(y1 - y0, 0.f);
    const float aa = fmaxf(a.z - a.x, 0.f) * fmaxf(a.w - a.y, 0.f);
    const float ab = fmaxf(b.z - b.x, 0.f) * fmaxf(b.w - b.y, 0.f);
    return inter / fmaxf(aa + ab - inter, 1e-6f);
}

// ---------------------------------------------------------------------------
// Kernel 1: per-chunk stats + zero-fill, with NMS fused into the last block.
// 4096 blocks (mask,chunk), 256 threads, 16 float4/thread, streaming.
// ---------------------------------------------------------------------------
__global__ __launch_bounds__(256) void stats_zero_nms_kernel(const float* __restrict__ logits,
                                                             float* __restrict__ out,
                                                             const float* __restrict__ iou_preds,
                                                             float* __restrict__ out_tail,
                                                             int write_keep, int write_boxes) {
    const int b = blockIdx.x;
    const int n = b >> 2;
    const int c = b & 3;
    const size_t off = (size_t)n * HW + (size_t)c * CHUNK;
    const float4* __restrict__ p = (const float4*)(logits + off);
    float4* __restrict__ o = (float4*)(out + off);
    const int t = threadIdx.x;

    int hi = 0, lo = 0;
    unsigned rowmask = 0u;
    int colbits = 0;
    const float4 z = make_float4(0.f, 0.f, 0.f, 0.f);

#pragma unroll 8
    for (int k = 0; k < 16; k++) {
        const int i4 = t + (k << 8);
        const float4 v = __ldcs(&p[i4]);
        __stcs(&o[i4], z);
        hi += (v.x > 1.f) + (v.y > 1.f) + (v.z > 1.f) + (v.w > 1.f);
        lo += (v.x > -1.f) + (v.y > -1.f) + (v.z > -1.f) + (v.w > -1.f);
        const int bits = (int)(v.x > 0.f) | ((int)(v.y > 0.f) << 1)
                       | ((int)(v.z > 0.f) << 2) | ((int)(v.w > 0.f) << 3);
        colbits |= bits;
        rowmask |= (bits ? 1u : 0u) << k;
    }

    int minx = WW, maxx = -1, miny = HH, maxy = -1;
    if (colbits) {
        const int x0 = (t & 63) << 2;
        minx = x0 + (__ffs(colbits) - 1);
        maxx = x0 + (31 - __clz(colbits));
    }
    if (rowmask) {
        const int r0 = (t >> 6) + (c << 6);
        miny = r0 + ((__ffs(rowmask) - 1) << 2);
        maxy = r0 + ((31 - __clz((int)rowmask)) << 2);
    }

    // warp reduce
#pragma unroll
    for (int oo = 16; oo > 0; oo >>= 1) {
        hi   += __shfl_xor_sync(0xffffffffu, hi, oo);
        lo   += __shfl_xor_sync(0xffffffffu, lo, oo);
        minx  = min(minx, __shfl_xor_sync(0xffffffffu, minx, oo));
        maxx  = max(maxx, __shfl_xor_sync(0xffffffffu, maxx, oo));
        miny  = min(miny, __shfl_xor_sync(0xffffffffu, miny, oo));
        maxy  = max(maxy, __shfl_xor_sync(0xffffffffu, maxy, oo));
    }

    __shared__ int s[8][6];
    __shared__ int s_islast;
    __shared__ int s_cnt;
    const int w = t >> 5, l = t & 31;
    if (l == 0) {
        s[w][0] = hi;   s[w][1] = lo;
        s[w][2] = minx; s[w][3] = maxx;
        s[w][4] = miny; s[w][5] = maxy;
    }
    __syncthreads();
    if (t == 0) {
#pragma unroll
        for (int i = 1; i < 8; i++) {
            hi += s[i][0]; lo += s[i][1];
            minx = min(minx, s[i][2]); maxx = max(maxx, s[i][3]);
            miny = min(miny, s[i][4]); maxy = max(maxy, s[i][5]);
        }
        int4* pp = (int4*)g_part;
        pp[b * 2]     = make_int4(hi, lo, minx, maxx);
        pp[b * 2 + 1] = make_int4(miny, maxy, 0, 0);

        __threadfence();                              // publish partials
        const unsigned v = atomicAdd(&g_done, 1u);
        s_islast = (v == (unsigned)(NBLK - 1));
        s_cnt = 0;
    }
    __syncthreads();
    if (!s_islast) return;

    // ======================= LAST BLOCK: fused NMS ========================
    __threadfence();                                  // acquire all partials

    // 1) combine + filter + compact (each thread: 4 masks)
    const int4* pp = (const int4*)g_part;
    for (int m = t; m < NM; m += 256) {
        int Hi = 0, Lo = 0, mnx = WW, mxx = -1, mny = HH, mxy = -1;
#pragma unroll
        for (int cc = 0; cc < 4; cc++) {
            const int4 a  = pp[(m * 4 + cc) * 2];
            const int4 bq = pp[(m * 4 + cc) * 2 + 1];
            Hi += a.x; Lo += a.y;
            mnx = min(mnx, a.z); mxx = max(mxx, a.w);
            mny = min(mny, bq.x); mxy = max(mxy, bq.y);
        }
        float4 box;
        if (mxx < 0) box = make_float4(0.f, 0.f, 0.f, 0.f);
        else box = make_float4((float)mnx, (float)mny, (float)mxx, (float)mxy);

        const float stab = (float)Hi / fmaxf((float)Lo, 1.0f);
        const float score = iou_preds[m];
        const int valid = (score > PRED_IOU_THRESH) && (stab >= STABILITY_THRESH);

        g_gated[m] = 0.f;                              // defaults (overwritten if kept)
        if (write_keep)  out_tail[m] = 0.0f;
        if (write_boxes) ((float4*)(out_tail + NM))[m] = box;

        if (valid) {
            const int slot = atomicAdd(&s_cnt, 1);
            g_cscore[slot] = score;
            g_cidx[slot]   = (short)m;
            g_cbox[slot]   = box;
        }
    }
    __syncthreads();
    const int V = s_cnt;

    // 2) stable descending rank (score desc, original index asc)
    for (int sidx = t; sidx < V; sidx += 256) {
        const float s0 = g_cscore[sidx];
        const short i0 = g_cidx[sidx];
        int rank = 0;
        for (int j = 0; j < V; j++) {
            const float sj = g_cscore[j];
            rank += (sj > s0) || (sj == s0 && g_cidx[j] < i0);
        }
        g_rb[rank]     = g_cbox[sidx];
        g_ridx[rank]   = i0;
        g_rscore[rank] = s0;
        g_rkeep[rank]  = 1;
    }
    __syncthreads();

    // 3) warp-serial greedy suppression (warp 0 only)
    if (t < 32) {
        for (int i = 0; i < V; i++) {
            if (g_rkeep[i]) {
                const float4 bi = g_rb[i];
                for (int j = i + 1 + t; j < V; j += 32) {
                    if (g_rkeep[j] && box_iou(bi, g_rb[j]) > BOX_NMS_THRESH)
                        g_rkeep[j] = 0;
                }
            }
            __syncwarp();
        }
    }
    __syncthreads();

    // 4) scatter results back to original order
    for (int sidx = t; sidx < V; sidx += 256) {
        if (g_rkeep[sidx]) {
            const int m = g_ridx[sidx];
            g_gated[m] = g_rscore[sidx];
            if (write_keep) out_tail[m] = 1.0f;
        }
    }
    __syncthreads();
    if (t == 0) {
        g_done = 0;                                    // reset for next replay
        __threadfence();
    }
}

// ---------------------------------------------------------------------------
// Kernel 2: sparse output fill — only kept masks do work (zeros already
// written by kernel 1). grid (NM, 16) x 256 threads x 4 float4: wide enough
// (~16 x kept blocks active) to hide DRAM latency; zombie blocks are one
// broadcast L2 read + exit.
// ---------------------------------------------------------------------------
__global__ __launch_bounds__(256) void out_kernel(const float* __restrict__ logits,
                                                  float* __restrict__ out) {
    const int n = blockIdx.x;
    const float g = g_gated[n];
    if (g == 0.f) return;

    const size_t off = (size_t)n * HW + (size_t)blockIdx.y * OCHUNK;
    const float4* __restrict__ p = (const float4*)(logits + off);
    float4* __restrict__ o = (float4*)(out + off);
    const int t = threadIdx.x;

#pragma unroll
    for (int k = 0; k < 4; k++) {
        const int i = t + (k << 8);
        float4 v = __ldcs(&p[i]);
        v.x = g / (1.f + __expf(-v.x));
        v.y = g / (1.f + __expf(-v.y));
        v.z = g / (1.f + __expf(-v.z));
        v.w = g / (1.f + __expf(-v.w));
        __stcs(&o[i], v);
    }
}

extern "C" void kernel_launch(void* const* d_in, const int* in_sizes, int n_in,
                              void* d_out, int out_size) {
    const float* logits = (const float*)d_in[0];
    const float* iou    = (const float*)d_in[1];
    if (n_in >= 2 && in_sizes[0] == NM) {      // defensive: input order swap
        logits = (const float*)d_in[1];
        iou    = (const float*)d_in[0];
    }
    float* out = (float*)d_out;

    const long long tail = (long long)out_size - (long long)NM * HW;
    const int write_keep  = tail >= NM;
    const int write_boxes = tail >= 5 * NM;

    stats_zero_nms_kernel<<<NBLK, 256>>>(logits, out, iou,
                                         out + (size_t)NM * HW, write_keep, write_boxes);
    out_kernel<<<dim3(NM, 16), 256>>>(logits, out);
}